// round 13
// baseline (speedup 1.0000x reference)
#include <cuda_runtime.h>
#include <cuda_fp16.h>
#include <math.h>
#include <stdint.h>

// Problem constants
#define VOCAB 32000
#define E_DIM 256
#define H_DIM 256
#define BATCH 64
#define T_LEN 2048
#define NCH 16                 // time chunks for parallel scan
#define TC (T_LEN / NCH)       // 128 timesteps per chunk

// ---------------- device scratch (allocation-free contract) ----------------
// Interleaved gate table: g_Gfz[v*256 + h] = (tanh(z), sigmoid(f)), 64 MB fp32
__device__ float2 g_Gfz[(size_t)VOCAB * H_DIM];
__device__ float g_cA[BATCH * NCH * H_DIM];          // per-chunk scan coeff A
__device__ float g_cB[BATCH * NCH * H_DIM];          // per-chunk scan coeff B
// B' rows j=0..511 interleaved (j=2h -> z col h, j=2h+1 -> f col h), K=256 fp16
__device__ __half g_Bhf[(size_t)512 * 256];

static __device__ __forceinline__ uint32_t smem_u32(const void* p) {
    uint32_t a;
    asm("{ .reg .u64 t; cvta.to.shared.u64 t, %1; cvt.u32.u64 %0, t; }" : "=r"(a) : "l"(p));
    return a;
}

// ===========================================================================
// convert_B: W fp32 -> interleaved fp16 rows (single rounding; A split carries
// the precision). 512 KB total, L2-resident for the GEMM.
// ===========================================================================
__global__ __launch_bounds__(512) void convert_B(const float* __restrict__ W)
{
    int k = blockIdx.x;          // 0..255 (W row)
    int j = threadIdx.x;         // 0..511 interleaved output row
    int src = (j & 1) * 256 + (j >> 1);   // even j -> z col, odd j -> f col
    g_Bhf[(size_t)j * 256 + k] = __float2half(W[(size_t)k * 768 + src]);
}

// ===========================================================================
// Kernel 1: fused-convert fp16 2-term split GEMM on mma.sync m16n8k16.
// Per CTA: D[128x128] over K=256 in 8 iters of 32. Each iter: cp.async raw
// fp32 emb chunk + fp16 B chunk; convert emb -> Ah/Al fp16 tiles in smem;
// one B-fragment load feeds BOTH Ah-MMAs and Al-MMAs (B' = [Bh|Bh] identity).
// 3-stage cp.async pipeline, 2 ahead.
// ===========================================================================
#define STG    28672             // per-stage: A32 (128x144B) + B (128x80B)
#define BOFF   18432             // B tile offset within a stage
#define AH_OFF 86016             // converted Ah tile (128x80B)
#define AL_OFF 96256             // converted Al tile (128x80B)
#define SBIAS  106496
#define SMTOT  107008
#define NKIT   8

__global__ __launch_bounds__(256, 2) void gemm_gates_mma(
    const float* __restrict__ emb,
    const float* __restrict__ bias)
{
    extern __shared__ __align__(128) char dsm[];
    float* sbias = (float*)(dsm + SBIAS);

    const int tid  = threadIdx.x;
    const int lane = tid & 31;
    const int wid  = tid >> 5;
    const int n0   = blockIdx.x * 128;   // interleaved col block (z/f mixed)
    const int m0   = blockIdx.y * 128;   // vocab row base
    const int warp_m = wid & 1;
    const int warp_n = wid >> 1;

    if (tid < 128) {
        int j = n0 + tid;
        sbias[tid] = bias[(j & 1) * 256 + (j >> 1)];
    }

    const uint32_t sbase = smem_u32(dsm);

    float c[4][4][4];
    #pragma unroll
    for (int i = 0; i < 4; i++)
        #pragma unroll
        for (int j = 0; j < 4; j++)
            #pragma unroll
            for (int q = 0; q < 4; q++) c[i][j][q] = 0.f;

    // ldmatrix lane-dependent base byte-offsets within an 80B-row fp16 tile
    const uint32_t a_lm = (uint32_t)((warp_m * 64 + (lane & 15)) * 80 + (lane >> 4) * 16);
    const uint32_t b_lm = (uint32_t)((warp_n * 32 + (lane >> 4) * 8 + (lane & 7)) * 80
                                     + ((lane >> 3) & 1) * 16);

    // convert mapping: thread -> (row, half-row of 16 floats)
    const int cv_row  = tid >> 1;
    const int cv_half = tid & 1;

#define ISSUE(kc) do {                                                             \
    if ((kc) < NKIT) {                                                             \
        int buf_ = (kc) % 3;                                                       \
        /* A: 128 rows x 32 fp32 (128B) as 8 16B chunks/row */                     \
        _Pragma("unroll")                                                          \
        for (int i_ = 0; i_ < 4; i_++) {                                           \
            int c_ = tid + i_ * 256;                                               \
            int row_ = c_ >> 3, chk_ = c_ & 7;                                     \
            uint32_t da_ = sbase + buf_ * STG + row_ * 144 + chk_ * 16;            \
            const float* ga_ = emb + (size_t)(m0 + row_) * E_DIM + (kc) * 32 + chk_ * 4; \
            asm volatile("cp.async.cg.shared.global [%0], [%1], 16;" :: "r"(da_), "l"(ga_)); \
        }                                                                          \
        /* B: 128 rows x 32 fp16 (64B) as 4 16B chunks/row */                      \
        _Pragma("unroll")                                                          \
        for (int i_ = 0; i_ < 2; i_++) {                                           \
            int c_ = tid + i_ * 256;                                               \
            int row_ = c_ >> 2, chk_ = c_ & 3;                                     \
            uint32_t db_ = sbase + buf_ * STG + BOFF + row_ * 80 + chk_ * 16;      \
            const __half* gb_ = g_Bhf + (size_t)(n0 + row_) * 256 + (kc) * 32 + chk_ * 8; \
            asm volatile("cp.async.cg.shared.global [%0], [%1], 16;" :: "r"(db_), "l"(gb_)); \
        }                                                                          \
    }                                                                              \
    asm volatile("cp.async.commit_group;");                                        \
} while (0)

    ISSUE(0); ISSUE(1);

    for (int it = 0; it < NKIT; ++it) {
        const int buf = it % 3;
        asm volatile("cp.async.wait_group 1;");
        __syncthreads();              // stage `it` visible; prev iter fully consumed
        ISSUE(it + 2);                // refills the buffer consumed last iter

        // ---- convert this stage's fp32 A chunk -> Ah / Al fp16 tiles ----
        {
            const char* src = dsm + buf * STG + cv_row * 144 + cv_half * 64;
            char* dst_h = dsm + AH_OFF + cv_row * 80 + cv_half * 32;
            char* dst_l = dsm + AL_OFF + cv_row * 80 + cv_half * 32;
            #pragma unroll
            for (int j = 0; j < 4; j++) {
                float4 x = *(const float4*)(src + j * 16);
                __half2 h01 = __floats2half2_rn(x.x, x.y);
                __half2 h23 = __floats2half2_rn(x.z, x.w);
                __half2 l01 = __floats2half2_rn(x.x - __half2float(__low2half(h01)),
                                                x.y - __half2float(__high2half(h01)));
                __half2 l23 = __floats2half2_rn(x.z - __half2float(__low2half(h23)),
                                                x.w - __half2float(__high2half(h23)));
                *(__half2*)(dst_h + j * 8)     = h01;
                *(__half2*)(dst_h + j * 8 + 4) = h23;
                *(__half2*)(dst_l + j * 8)     = l01;
                *(__half2*)(dst_l + j * 8 + 4) = l23;
            }
        }
        __syncthreads();              // converted tiles visible to all warps

        #pragma unroll
        for (int ks = 0; ks < 2; ks++) {
            uint32_t a[4][4], b[4][2];
            // B fragments (shared by Ah and Al products)
            #pragma unroll
            for (int np = 0; np < 2; np++) {
                uint32_t addr = sbase + buf * STG + BOFF + b_lm + np * (16 * 80) + ks * 32;
                asm volatile("ldmatrix.sync.aligned.m8n8.x4.shared.b16 {%0,%1,%2,%3}, [%4];"
                             : "=r"(b[np * 2][0]), "=r"(b[np * 2][1]),
                               "=r"(b[np * 2 + 1][0]), "=r"(b[np * 2 + 1][1])
                             : "r"(addr));
            }
            // Ah product
            #pragma unroll
            for (int mt = 0; mt < 4; mt++) {
                uint32_t addr = sbase + AH_OFF + a_lm + mt * (16 * 80) + ks * 32;
                asm volatile("ldmatrix.sync.aligned.m8n8.x4.shared.b16 {%0,%1,%2,%3}, [%4];"
                             : "=r"(a[mt][0]), "=r"(a[mt][1]), "=r"(a[mt][2]), "=r"(a[mt][3])
                             : "r"(addr));
            }
            #pragma unroll
            for (int mt = 0; mt < 4; mt++)
                #pragma unroll
                for (int nt = 0; nt < 4; nt++)
                    asm volatile(
                        "mma.sync.aligned.m16n8k16.row.col.f32.f16.f16.f32 "
                        "{%0,%1,%2,%3}, {%4,%5,%6,%7}, {%8,%9}, {%0,%1,%2,%3};"
                        : "+f"(c[mt][nt][0]), "+f"(c[mt][nt][1]),
                          "+f"(c[mt][nt][2]), "+f"(c[mt][nt][3])
                        : "r"(a[mt][0]), "r"(a[mt][1]), "r"(a[mt][2]), "r"(a[mt][3]),
                          "r"(b[nt][0]), "r"(b[nt][1]));
            // Al product (reuses b fragments)
            #pragma unroll
            for (int mt = 0; mt < 4; mt++) {
                uint32_t addr = sbase + AL_OFF + a_lm + mt * (16 * 80) + ks * 32;
                asm volatile("ldmatrix.sync.aligned.m8n8.x4.shared.b16 {%0,%1,%2,%3}, [%4];"
                             : "=r"(a[mt][0]), "=r"(a[mt][1]), "=r"(a[mt][2]), "=r"(a[mt][3])
                             : "r"(addr));
            }
            #pragma unroll
            for (int mt = 0; mt < 4; mt++)
                #pragma unroll
                for (int nt = 0; nt < 4; nt++)
                    asm volatile(
                        "mma.sync.aligned.m16n8k16.row.col.f32.f16.f16.f32 "
                        "{%0,%1,%2,%3}, {%4,%5,%6,%7}, {%8,%9}, {%0,%1,%2,%3};"
                        : "+f"(c[mt][nt][0]), "+f"(c[mt][nt][1]),
                          "+f"(c[mt][nt][2]), "+f"(c[mt][nt][3])
                        : "r"(a[mt][0]), "r"(a[mt][1]), "r"(a[mt][2]), "r"(a[mt][3]),
                          "r"(b[nt][0]), "r"(b[nt][1]));
        }
    }
#undef ISSUE

    // ---- Epilogue: bias + activation, one float2 (z,f) per h to g_Gfz ----
    #pragma unroll
    for (int mt = 0; mt < 4; mt++) {
        int m = m0 + warp_m * 64 + mt * 16 + (lane >> 2);
        #pragma unroll
        for (int nt = 0; nt < 4; nt++) {
            int nloc = warp_n * 32 + nt * 8 + (lane & 3) * 2;   // even = z, odd = f
            int h = (n0 + nloc) >> 1;
            float vz0 = c[mt][nt][0] + sbias[nloc];
            float vf0 = c[mt][nt][1] + sbias[nloc + 1];
            float vz1 = c[mt][nt][2] + sbias[nloc];
            float vf1 = c[mt][nt][3] + sbias[nloc + 1];
            float2 o0, o1;
            o0.x = tanhf(vz0); o0.y = 1.f / (1.f + expf(-vf0));
            o1.x = tanhf(vz1); o1.y = 1.f / (1.f + expf(-vf1));
            g_Gfz[(size_t)m * H_DIM + h]       = o0;
            g_Gfz[(size_t)(m + 8) * H_DIM + h] = o1;
        }
    }
}

// ---------------------------------------------------------------------------
// Kernel 2: parallel chunked scan; one 8B gather per (t,h) from g_Gfz.
// At the chip LTS cap — at its floor for an fp32 table.
// ---------------------------------------------------------------------------
__global__ __launch_bounds__(256) void scan_chunks(const int* __restrict__ X)
{
    const int chunk = blockIdx.x;
    const int b     = blockIdx.y;
    const int h     = threadIdx.x;

    __shared__ int toks[TC];
    if (h < TC) toks[h] = __ldg(&X[b * T_LEN + chunk * TC + h]);
    __syncthreads();

    float A = 1.f, Bc = 0.f;
    #pragma unroll 16
    for (int t = 0; t < TC; t++) {
        float2 p = __ldg(&g_Gfz[(size_t)toks[t] * H_DIM + h]);
        float z = p.x, f = p.y;
        A *= f;
        Bc = fmaf(f, Bc - z, z);
    }

    int idx = (b * NCH + chunk) * H_DIM + h;
    g_cA[idx] = A;
    g_cB[idx] = Bc;
}

// ---------------------------------------------------------------------------
// Kernel 3: chunk combine + o-gate + output projection (unchanged).
// ---------------------------------------------------------------------------
__global__ __launch_bounds__(256) void finalize(
    const int*   __restrict__ X,
    const float* __restrict__ emb,
    const float* __restrict__ W,
    const float* __restrict__ bias,
    const float* __restrict__ c0,
    const float* __restrict__ Wout,
    const float* __restrict__ bout,
    float*       __restrict__ out)
{
    const int b = blockIdx.x;
    const int h = threadIdx.x;

    __shared__ float xrow[E_DIM];
    __shared__ float red[H_DIM];

    const int tok_last = X[b * T_LEN + (T_LEN - 1)];
    xrow[h] = emb[(size_t)tok_last * E_DIM + h];
    __syncthreads();

    float c = c0[b * H_DIM + h];
    #pragma unroll
    for (int j = 0; j < NCH; j++) {
        int idx = (b * NCH + j) * H_DIM + h;
        c = fmaf(g_cA[idx], c, g_cB[idx]);
    }

    float a0 = bias[512 + h], a1 = 0.f, a2 = 0.f, a3 = 0.f;
    #pragma unroll 8
    for (int e = 0; e < E_DIM; e += 4) {
        a0 = fmaf(xrow[e + 0], W[(size_t)(e + 0) * 768 + 512 + h], a0);
        a1 = fmaf(xrow[e + 1], W[(size_t)(e + 1) * 768 + 512 + h], a1);
        a2 = fmaf(xrow[e + 2], W[(size_t)(e + 2) * 768 + 512 + h], a2);
        a3 = fmaf(xrow[e + 3], W[(size_t)(e + 3) * 768 + 512 + h], a3);
    }
    float go = (a0 + a1) + (a2 + a3);
    float o  = 1.f / (1.f + expf(-go));

    red[h] = o * c * Wout[h];
    __syncthreads();

    #pragma unroll
    for (int s = 128; s > 0; s >>= 1) {
        if (h < s) red[h] += red[h + s];
        __syncthreads();
    }
    if (h == 0) out[b] = red[0] + bout[0];
}

// ---------------------------------------------------------------------------
extern "C" void kernel_launch(void* const* d_in, const int* in_sizes, int n_in,
                              void* d_out, int out_size)
{
    const int*   X    = (const int*)  d_in[0];   // [B, T] int32
    const float* emb  = (const float*)d_in[1];   // [VOCAB, E]
    const float* Wq   = (const float*)d_in[2];   // [E, 3H]
    const float* bq   = (const float*)d_in[3];   // [3H]
    const float* c0   = (const float*)d_in[4];   // [B, H]
    const float* Wout = (const float*)d_in[5];   // [H, 1]
    const float* bout = (const float*)d_in[6];   // [1]
    float*       out  = (float*)d_out;           // [B, 1]

    (void)in_sizes; (void)n_in; (void)out_size;

    cudaFuncSetAttribute(gemm_gates_mma, cudaFuncAttributeMaxDynamicSharedMemorySize, SMTOT);

    // 0) B conversion only (A converted in-GEMM)
    convert_B<<<256, 512>>>(Wq);

    // 1) Gate-table GEMM, fused A-split, fp16 2-term, shared B fragments
    dim3 ggrid(4, VOCAB / 128);                  // (4, 250)
    gemm_gates_mma<<<ggrid, 256, SMTOT>>>(emb, bq);

    // 2) Parallel chunked scan over time
    dim3 sgrid(NCH, BATCH);                      // (16, 64)
    scan_chunks<<<sgrid, 256>>>(X);

    // 3) Combine + o-gate + output projection
    finalize<<<BATCH, 256>>>(X, emb, Wq, bq, c0, Wout, bout, out);
}

// round 14
// speedup vs baseline: 1.5031x; 1.5031x over previous
#include <cuda_runtime.h>
#include <cuda_fp16.h>
#include <math.h>
#include <stdint.h>

// Problem constants
#define VOCAB 32000
#define E_DIM 256
#define H_DIM 256
#define BATCH 64
#define T_LEN 2048
#define NCH 16                 // time chunks for parallel scan
#define TC (T_LEN / NCH)       // 128 timesteps per chunk

// ---------------- device scratch (allocation-free contract) ----------------
// Interleaved gate table: g_Gfz[v*256 + h] = (tanh(z), sigmoid(f)), 64 MB fp32
__device__ float2 g_Gfz[(size_t)VOCAB * H_DIM];
__device__ float g_cA[BATCH * NCH * H_DIM];          // per-chunk scan coeff A
__device__ float g_cB[BATCH * NCH * H_DIM];          // per-chunk scan coeff B
__device__ float g_oB[BATCH * H_DIM];                // o-gate for last token, per b
// A' = [Ah(256) | Al(256)] fp16 per vocab row (2-term split of emb)
__device__ __half g_Ahf[(size_t)VOCAB * 512];
// B' rows j=0..511 interleaved (j=2h -> z col h, j=2h+1 -> f col h),
// along K': [Bh(256) | Bh(256)] (duplicate so kB = kA, fully linear)
__device__ __half g_Bhf[(size_t)512 * 512];

static __device__ __forceinline__ uint32_t smem_u32(const void* p) {
    uint32_t a;
    asm("{ .reg .u64 t; cvta.to.shared.u64 t, %1; cvt.u32.u64 %0, t; }" : "=r"(a) : "l"(p));
    return a;
}

// ===========================================================================
// Convert kernels: fp32 -> 2-term fp16 split, GEMM-friendly layouts (R11).
// ===========================================================================
__global__ __launch_bounds__(256) void convert_A(const float* __restrict__ emb)
{
    int idx = blockIdx.x * 256 + threadIdx.x;   // one float4 each; 32000*64 total
    int v = idx >> 6;
    int k = (idx & 63) * 4;
    float4 x = *(const float4*)(emb + (size_t)v * E_DIM + k);
    __half2 h01 = __floats2half2_rn(x.x, x.y);
    __half2 h23 = __floats2half2_rn(x.z, x.w);
    __half2 l01 = __floats2half2_rn(x.x - __half2float(__low2half(h01)),
                                    x.y - __half2float(__high2half(h01)));
    __half2 l23 = __floats2half2_rn(x.z - __half2float(__low2half(h23)),
                                    x.w - __half2float(__high2half(h23)));
    __half* row = g_Ahf + (size_t)v * 512;
    *(__half2*)(row + k)           = h01;
    *(__half2*)(row + k + 2)       = h23;
    *(__half2*)(row + 256 + k)     = l01;
    *(__half2*)(row + 256 + k + 2) = l23;
}

__global__ __launch_bounds__(512) void convert_B(const float* __restrict__ W)
{
    int k = blockIdx.x;          // 0..255 (W row)
    int j = threadIdx.x;         // 0..511 interleaved output row
    int src = (j & 1) * 256 + (j >> 1);   // even j -> z col, odd j -> f col
    float v = W[(size_t)k * 768 + src];
    __half h = __float2half(v);
    __half* row = g_Bhf + (size_t)j * 512;
    row[k]       = h;   // pairs with Ah (iters 0-7)
    row[k + 256] = h;   // pairs with Al (iters 8-15)
}

// ===========================================================================
// Kernel 1: fp16 2-term split GEMM (exact R11 kernel — measured at HMMA floor).
// 4-stage cp.async pipeline, one __syncthreads per K-iteration, K'=512.
// ===========================================================================
#define STG   20480              // per-stage stride (A tile + B tile)
#define BOFF  10240              // B tile offset within a stage
#define SBIAS 81920              // bias offset
#define SMTOT (SBIAS + 512)
#define NKIT  16

__global__ __launch_bounds__(256, 2) void gemm_gates_mma(const float* __restrict__ bias)
{
    extern __shared__ __align__(128) char dsm[];
    float* sbias = (float*)(dsm + SBIAS);

    const int tid  = threadIdx.x;
    const int lane = tid & 31;
    const int wid  = tid >> 5;
    const int n0   = blockIdx.x * 128;   // interleaved col block (z/f mixed)
    const int m0   = blockIdx.y * 128;   // vocab row base
    const int warp_m = wid & 1;
    const int warp_n = wid >> 1;

    if (tid < 128) {
        int j = n0 + tid;
        sbias[tid] = bias[(j & 1) * 256 + (j >> 1)];
    }

    const uint32_t sbase = smem_u32(dsm);

    // cp.async mapping: per tile 512 16B-chunks; row = tid>>2 (+64), chunk = tid&3
    const int ld_row = tid >> 2;
    const int ld_chk = tid & 3;

    float c[4][4][4];
    #pragma unroll
    for (int i = 0; i < 4; i++)
        #pragma unroll
        for (int j = 0; j < 4; j++)
            #pragma unroll
            for (int q = 0; q < 4; q++) c[i][j][q] = 0.f;

    // ldmatrix lane-dependent base byte-offsets (stage offset added later)
    const uint32_t a_lm = (uint32_t)((warp_m * 64 + (lane & 15)) * 80 + (lane >> 4) * 16);
    const uint32_t b_lm = (uint32_t)((warp_n * 32 + (lane >> 4) * 8 + (lane & 7)) * 80
                                     + ((lane >> 3) & 1) * 16);

#define ISSUE(it) do {                                                             \
    if ((it) < NKIT) {                                                             \
        int buf_ = (it) & 3;                                                       \
        int kk_ = (it) * 32;                                                       \
        _Pragma("unroll")                                                          \
        for (int r_ = 0; r_ < 2; r_++) {                                           \
            int row_ = ld_row + r_ * 64;                                           \
            uint32_t da_ = sbase + buf_ * STG + row_ * 80 + ld_chk * 16;           \
            const __half* ga_ = g_Ahf + (size_t)(m0 + row_) * 512 + kk_ + ld_chk * 8; \
            asm volatile("cp.async.cg.shared.global [%0], [%1], 16;" :: "r"(da_), "l"(ga_)); \
            uint32_t db_ = sbase + buf_ * STG + BOFF + row_ * 80 + ld_chk * 16;    \
            const __half* gb_ = g_Bhf + (size_t)(n0 + row_) * 512 + kk_ + ld_chk * 8; \
            asm volatile("cp.async.cg.shared.global [%0], [%1], 16;" :: "r"(db_), "l"(gb_)); \
        }                                                                          \
    }                                                                              \
    asm volatile("cp.async.commit_group;");                                        \
} while (0)

    ISSUE(0); ISSUE(1); ISSUE(2);

    for (int it = 0; it < NKIT; ++it) {
        const int buf = it & 3;
        asm volatile("cp.async.wait_group 2;");
        __syncthreads();              // stage `it` visible; all warps done with it-1
        ISSUE(it + 3);                // fills buf (it-1)&3 — safe after the sync

        #pragma unroll
        for (int ks = 0; ks < 2; ks++) {
            uint32_t a[4][4], b[4][2];
            #pragma unroll
            for (int mt = 0; mt < 4; mt++) {
                uint32_t addr = sbase + buf * STG + a_lm + mt * (16 * 80) + ks * 32;
                asm volatile("ldmatrix.sync.aligned.m8n8.x4.shared.b16 {%0,%1,%2,%3}, [%4];"
                             : "=r"(a[mt][0]), "=r"(a[mt][1]), "=r"(a[mt][2]), "=r"(a[mt][3])
                             : "r"(addr));
            }
            #pragma unroll
            for (int np = 0; np < 2; np++) {
                uint32_t addr = sbase + buf * STG + BOFF + b_lm + np * (16 * 80) + ks * 32;
                asm volatile("ldmatrix.sync.aligned.m8n8.x4.shared.b16 {%0,%1,%2,%3}, [%4];"
                             : "=r"(b[np * 2][0]), "=r"(b[np * 2][1]),
                               "=r"(b[np * 2 + 1][0]), "=r"(b[np * 2 + 1][1])
                             : "r"(addr));
            }
            #pragma unroll
            for (int mt = 0; mt < 4; mt++)
                #pragma unroll
                for (int nt = 0; nt < 4; nt++)
                    asm volatile(
                        "mma.sync.aligned.m16n8k16.row.col.f32.f16.f16.f32 "
                        "{%0,%1,%2,%3}, {%4,%5,%6,%7}, {%8,%9}, {%0,%1,%2,%3};"
                        : "+f"(c[mt][nt][0]), "+f"(c[mt][nt][1]),
                          "+f"(c[mt][nt][2]), "+f"(c[mt][nt][3])
                        : "r"(a[mt][0]), "r"(a[mt][1]), "r"(a[mt][2]), "r"(a[mt][3]),
                          "r"(b[nt][0]), "r"(b[nt][1]));
        }
    }
#undef ISSUE

    // ---- Epilogue: bias + activation, one float2 (z,f) per h to g_Gfz ----
    #pragma unroll
    for (int mt = 0; mt < 4; mt++) {
        int m = m0 + warp_m * 64 + mt * 16 + (lane >> 2);
        #pragma unroll
        for (int nt = 0; nt < 4; nt++) {
            int nloc = warp_n * 32 + nt * 8 + (lane & 3) * 2;   // even = z, odd = f
            int h = (n0 + nloc) >> 1;
            float vz0 = c[mt][nt][0] + sbias[nloc];
            float vf0 = c[mt][nt][1] + sbias[nloc + 1];
            float vz1 = c[mt][nt][2] + sbias[nloc];
            float vf1 = c[mt][nt][3] + sbias[nloc + 1];
            float2 o0, o1;
            o0.x = tanhf(vz0); o0.y = 1.f / (1.f + expf(-vf0));
            o1.x = tanhf(vz1); o1.y = 1.f / (1.f + expf(-vf1));
            g_Gfz[(size_t)m * H_DIM + h]       = o0;
            g_Gfz[(size_t)(m + 8) * H_DIM + h] = o1;
        }
    }
}

// ---------------------------------------------------------------------------
// Kernel 2: parallel chunked scan (1024 CTAs, at LTS cap) + 64 overlapped
// o-gate CTAs (blockIdx.x == NCH) hidden inside the scan wave.
// ---------------------------------------------------------------------------
__global__ __launch_bounds__(256) void scan_chunks(
    const int* __restrict__ X,
    const float* __restrict__ emb,
    const float* __restrict__ W,      // [256, 768]
    const float* __restrict__ bias)   // [768]
{
    const int chunk = blockIdx.x;
    const int b     = blockIdx.y;
    const int h     = threadIdx.x;

    if (chunk == NCH) {
        // ---- o-gate CTA: o_b[h] = sigmoid(emb[tok_last].W[:,512+h] + bias) ----
        __shared__ float xrow[E_DIM];
        const int tok_last = X[b * T_LEN + (T_LEN - 1)];
        xrow[h] = emb[(size_t)tok_last * E_DIM + h];
        __syncthreads();

        float a0 = bias[512 + h], a1 = 0.f, a2 = 0.f, a3 = 0.f;
        #pragma unroll 8
        for (int e = 0; e < E_DIM; e += 4) {
            a0 = fmaf(xrow[e + 0], __ldg(&W[(size_t)(e + 0) * 768 + 512 + h]), a0);
            a1 = fmaf(xrow[e + 1], __ldg(&W[(size_t)(e + 1) * 768 + 512 + h]), a1);
            a2 = fmaf(xrow[e + 2], __ldg(&W[(size_t)(e + 2) * 768 + 512 + h]), a2);
            a3 = fmaf(xrow[e + 3], __ldg(&W[(size_t)(e + 3) * 768 + 512 + h]), a3);
        }
        float go = (a0 + a1) + (a2 + a3);
        g_oB[b * H_DIM + h] = 1.f / (1.f + expf(-go));
        return;
    }

    __shared__ int toks[TC];
    if (h < TC) toks[h] = __ldg(&X[b * T_LEN + chunk * TC + h]);
    __syncthreads();

    float A = 1.f, Bc = 0.f;
    #pragma unroll 16
    for (int t = 0; t < TC; t++) {
        float2 p = __ldg(&g_Gfz[(size_t)toks[t] * H_DIM + h]);
        float z = p.x, f = p.y;
        A *= f;
        Bc = fmaf(f, Bc - z, z);
    }

    int idx = (b * NCH + chunk) * H_DIM + h;
    g_cA[idx] = A;
    g_cB[idx] = Bc;
}

// ---------------------------------------------------------------------------
// Kernel 3: slim finalize — batched chunk-combine prefetch, precomputed o,
// output projection with block reduction. One CTA per batch row.
// ---------------------------------------------------------------------------
__global__ __launch_bounds__(256) void finalize(
    const float* __restrict__ c0,     // [B, H]
    const float* __restrict__ Wout,   // [H]
    const float* __restrict__ bout,   // [1]
    float*       __restrict__ out)    // [B]
{
    const int b = blockIdx.x;
    const int h = threadIdx.x;

    __shared__ float red[H_DIM];

    // Batched prefetch: 32 independent loads, single latency exposure
    float As[NCH], Bs[NCH];
    #pragma unroll
    for (int j = 0; j < NCH; j++) {
        int idx = (b * NCH + j) * H_DIM + h;
        As[j] = __ldg(&g_cA[idx]);
        Bs[j] = __ldg(&g_cB[idx]);
    }
    float c = __ldg(&c0[b * H_DIM + h]);
    #pragma unroll
    for (int j = 0; j < NCH; j++) c = fmaf(As[j], c, Bs[j]);

    red[h] = __ldg(&g_oB[b * H_DIM + h]) * c * __ldg(&Wout[h]);
    __syncthreads();

    #pragma unroll
    for (int s = 128; s > 0; s >>= 1) {
        if (h < s) red[h] += red[h + s];
        __syncthreads();
    }
    if (h == 0) out[b] = red[0] + bout[0];
}

// ---------------------------------------------------------------------------
extern "C" void kernel_launch(void* const* d_in, const int* in_sizes, int n_in,
                              void* d_out, int out_size)
{
    const int*   X    = (const int*)  d_in[0];   // [B, T] int32
    const float* emb  = (const float*)d_in[1];   // [VOCAB, E]
    const float* Wq   = (const float*)d_in[2];   // [E, 3H]
    const float* bq   = (const float*)d_in[3];   // [3H]
    const float* c0   = (const float*)d_in[4];   // [B, H]
    const float* Wout = (const float*)d_in[5];   // [H, 1]
    const float* bout = (const float*)d_in[6];   // [1]
    float*       out  = (float*)d_out;           // [B, 1]

    (void)in_sizes; (void)n_in; (void)out_size;

    cudaFuncSetAttribute(gemm_gates_mma, cudaFuncAttributeMaxDynamicSharedMemorySize, SMTOT);

    // 0) fp16 split conversions (A': [Ah|Al], B': interleaved [Bh|Bh])
    convert_A<<<VOCAB * 64 / 256, 256>>>(emb);   // 8000 blocks
    convert_B<<<256, 512>>>(Wq);

    // 1) Gate-table GEMM on tensor cores, K'=512 fp16 2-term split (R11)
    dim3 ggrid(4, VOCAB / 128);                  // (4, 250)
    gemm_gates_mma<<<ggrid, 256, SMTOT>>>(bq);

    // 2) Parallel chunked scan + overlapped o-gate CTAs
    dim3 sgrid(NCH + 1, BATCH);                  // (17, 64)
    scan_chunks<<<sgrid, 256>>>(X, emb, Wq, bq);

    // 3) Slim combine + output projection
    finalize<<<BATCH, 256>>>(c0, Wout, bout, out);
}

// round 15
// speedup vs baseline: 2.1667x; 1.4415x over previous
#include <cuda_runtime.h>
#include <cuda_fp16.h>
#include <math.h>
#include <stdint.h>

// Problem constants
#define VOCAB 32000
#define E_DIM 256
#define H_DIM 256
#define BATCH 64
#define T_LEN 2048
#define NCH 16                 // time chunks for parallel scan
#define TC (T_LEN / NCH)       // 128 timesteps per chunk

// ---------------- device scratch (allocation-free contract) ----------------
// Interleaved gate table: g_Gfz[v*256 + h] = (tanh(z), sigmoid(f)), 64 MB fp32
__device__ float2 g_Gfz[(size_t)VOCAB * H_DIM];
__device__ float g_cA[BATCH * NCH * H_DIM];          // per-chunk scan coeff A
__device__ float g_cB[BATCH * NCH * H_DIM];          // per-chunk scan coeff B
__device__ float g_oB[BATCH * H_DIM];                // o-gate for last token, per b
// A = emb rounded once to fp16, [VOCAB, 256] (16.4 MB)
__device__ __half g_Ahf[(size_t)VOCAB * 256];
// B rows j=0..511 interleaved (j=2h -> z col h, j=2h+1 -> f col h), K=256 fp16
__device__ __half g_Bhf[(size_t)512 * 256];

static __device__ __forceinline__ uint32_t smem_u32(const void* p) {
    uint32_t a;
    asm("{ .reg .u64 t; cvta.to.shared.u64 t, %1; cvt.u32.u64 %0, t; }" : "=r"(a) : "l"(p));
    return a;
}

// ===========================================================================
// Convert kernels: fp32 -> fp16 (single rounding), GEMM-friendly layouts.
// ===========================================================================
__global__ __launch_bounds__(256) void convert_A(const float* __restrict__ emb)
{
    int idx = blockIdx.x * 256 + threadIdx.x;   // one float4 each; 32000*64 total
    int v = idx >> 6;
    int k = (idx & 63) * 4;
    float4 x = *(const float4*)(emb + (size_t)v * E_DIM + k);
    __half2 h01 = __floats2half2_rn(x.x, x.y);
    __half2 h23 = __floats2half2_rn(x.z, x.w);
    __half* row = g_Ahf + (size_t)v * 256;
    *(__half2*)(row + k)     = h01;
    *(__half2*)(row + k + 2) = h23;
}

__global__ __launch_bounds__(512) void convert_B(const float* __restrict__ W)
{
    int k = blockIdx.x;          // 0..255 (W row)
    int j = threadIdx.x;         // 0..511 interleaved output row
    int src = (j & 1) * 256 + (j >> 1);   // even j -> z col, odd j -> f col
    g_Bhf[(size_t)j * 256 + k] = __float2half(W[(size_t)k * 768 + src]);
}

// ===========================================================================
// Kernel 1: fp16 GEMM on mma.sync m16n8k16, 4-stage cp.async pipeline,
// one __syncthreads per K-iteration. Per CTA: D[128x128] over K=256 (8 iters).
// ===========================================================================
#define STG   20480              // per-stage stride (A tile + B tile)
#define BOFF  10240              // B tile offset within a stage
#define SBIAS 81920              // bias offset
#define SMTOT (SBIAS + 512)
#define NKIT  8

__global__ __launch_bounds__(256, 2) void gemm_gates_mma(const float* __restrict__ bias)
{
    extern __shared__ __align__(128) char dsm[];
    float* sbias = (float*)(dsm + SBIAS);

    const int tid  = threadIdx.x;
    const int lane = tid & 31;
    const int wid  = tid >> 5;
    const int n0   = blockIdx.x * 128;   // interleaved col block (z/f mixed)
    const int m0   = blockIdx.y * 128;   // vocab row base
    const int warp_m = wid & 1;
    const int warp_n = wid >> 1;

    if (tid < 128) {
        int j = n0 + tid;
        sbias[tid] = bias[(j & 1) * 256 + (j >> 1)];
    }

    const uint32_t sbase = smem_u32(dsm);

    // cp.async mapping: per tile 512 16B-chunks; row = tid>>2 (+64), chunk = tid&3
    const int ld_row = tid >> 2;
    const int ld_chk = tid & 3;

    float c[4][4][4];
    #pragma unroll
    for (int i = 0; i < 4; i++)
        #pragma unroll
        for (int j = 0; j < 4; j++)
            #pragma unroll
            for (int q = 0; q < 4; q++) c[i][j][q] = 0.f;

    // ldmatrix lane-dependent base byte-offsets (stage offset added later)
    const uint32_t a_lm = (uint32_t)((warp_m * 64 + (lane & 15)) * 80 + (lane >> 4) * 16);
    const uint32_t b_lm = (uint32_t)((warp_n * 32 + (lane >> 4) * 8 + (lane & 7)) * 80
                                     + ((lane >> 3) & 1) * 16);

#define ISSUE(it) do {                                                             \
    if ((it) < NKIT) {                                                             \
        int buf_ = (it) & 3;                                                       \
        int kk_ = (it) * 32;                                                       \
        _Pragma("unroll")                                                          \
        for (int r_ = 0; r_ < 2; r_++) {                                           \
            int row_ = ld_row + r_ * 64;                                           \
            uint32_t da_ = sbase + buf_ * STG + row_ * 80 + ld_chk * 16;           \
            const __half* ga_ = g_Ahf + (size_t)(m0 + row_) * 256 + kk_ + ld_chk * 8; \
            asm volatile("cp.async.cg.shared.global [%0], [%1], 16;" :: "r"(da_), "l"(ga_)); \
            uint32_t db_ = sbase + buf_ * STG + BOFF + row_ * 80 + ld_chk * 16;    \
            const __half* gb_ = g_Bhf + (size_t)(n0 + row_) * 256 + kk_ + ld_chk * 8; \
            asm volatile("cp.async.cg.shared.global [%0], [%1], 16;" :: "r"(db_), "l"(gb_)); \
        }                                                                          \
    }                                                                              \
    asm volatile("cp.async.commit_group;");                                        \
} while (0)

    ISSUE(0); ISSUE(1); ISSUE(2);

    for (int it = 0; it < NKIT; ++it) {
        const int buf = it & 3;
        asm volatile("cp.async.wait_group 2;");
        __syncthreads();              // stage `it` visible; all warps done with it-1
        ISSUE(it + 3);                // fills buf (it-1)&3 — safe after the sync

        #pragma unroll
        for (int ks = 0; ks < 2; ks++) {
            uint32_t a[4][4], b[4][2];
            #pragma unroll
            for (int mt = 0; mt < 4; mt++) {
                uint32_t addr = sbase + buf * STG + a_lm + mt * (16 * 80) + ks * 32;
                asm volatile("ldmatrix.sync.aligned.m8n8.x4.shared.b16 {%0,%1,%2,%3}, [%4];"
                             : "=r"(a[mt][0]), "=r"(a[mt][1]), "=r"(a[mt][2]), "=r"(a[mt][3])
                             : "r"(addr));
            }
            #pragma unroll
            for (int np = 0; np < 2; np++) {
                uint32_t addr = sbase + buf * STG + BOFF + b_lm + np * (16 * 80) + ks * 32;
                asm volatile("ldmatrix.sync.aligned.m8n8.x4.shared.b16 {%0,%1,%2,%3}, [%4];"
                             : "=r"(b[np * 2][0]), "=r"(b[np * 2][1]),
                               "=r"(b[np * 2 + 1][0]), "=r"(b[np * 2 + 1][1])
                             : "r"(addr));
            }
            #pragma unroll
            for (int mt = 0; mt < 4; mt++)
                #pragma unroll
                for (int nt = 0; nt < 4; nt++)
                    asm volatile(
                        "mma.sync.aligned.m16n8k16.row.col.f32.f16.f16.f32 "
                        "{%0,%1,%2,%3}, {%4,%5,%6,%7}, {%8,%9}, {%0,%1,%2,%3};"
                        : "+f"(c[mt][nt][0]), "+f"(c[mt][nt][1]),
                          "+f"(c[mt][nt][2]), "+f"(c[mt][nt][3])
                        : "r"(a[mt][0]), "r"(a[mt][1]), "r"(a[mt][2]), "r"(a[mt][3]),
                          "r"(b[nt][0]), "r"(b[nt][1]));
        }
    }
#undef ISSUE

    // ---- Epilogue: bias + activation, one float2 (z,f) per h to g_Gfz ----
    #pragma unroll
    for (int mt = 0; mt < 4; mt++) {
        int m = m0 + warp_m * 64 + mt * 16 + (lane >> 2);
        #pragma unroll
        for (int nt = 0; nt < 4; nt++) {
            int nloc = warp_n * 32 + nt * 8 + (lane & 3) * 2;   // even = z, odd = f
            int h = (n0 + nloc) >> 1;
            float vz0 = c[mt][nt][0] + sbias[nloc];
            float vf0 = c[mt][nt][1] + sbias[nloc + 1];
            float vz1 = c[mt][nt][2] + sbias[nloc];
            float vf1 = c[mt][nt][3] + sbias[nloc + 1];
            float2 o0, o1;
            o0.x = tanhf(vz0); o0.y = 1.f / (1.f + expf(-vf0));
            o1.x = tanhf(vz1); o1.y = 1.f / (1.f + expf(-vf1));
            g_Gfz[(size_t)m * H_DIM + h]       = o0;
            g_Gfz[(size_t)(m + 8) * H_DIM + h] = o1;
        }
    }
}

// ---------------------------------------------------------------------------
// Kernel 2: parallel chunked scan (1024 CTAs, at LTS cap) + 64 overlapped
// o-gate CTAs (blockIdx.x == NCH) hidden inside the scan wave.
// ---------------------------------------------------------------------------
__global__ __launch_bounds__(256) void scan_chunks(
    const int* __restrict__ X,
    const float* __restrict__ emb,
    const float* __restrict__ W,      // [256, 768]
    const float* __restrict__ bias)   // [768]
{
    const int chunk = blockIdx.x;
    const int b     = blockIdx.y;
    const int h     = threadIdx.x;

    if (chunk == NCH) {
        // ---- o-gate CTA: o_b[h] = sigmoid(emb[tok_last].W[:,512+h] + bias) ----
        __shared__ float xrow[E_DIM];
        const int tok_last = X[b * T_LEN + (T_LEN - 1)];
        xrow[h] = emb[(size_t)tok_last * E_DIM + h];
        __syncthreads();

        float a0 = bias[512 + h], a1 = 0.f, a2 = 0.f, a3 = 0.f;
        #pragma unroll 8
        for (int e = 0; e < E_DIM; e += 4) {
            a0 = fmaf(xrow[e + 0], __ldg(&W[(size_t)(e + 0) * 768 + 512 + h]), a0);
            a1 = fmaf(xrow[e + 1], __ldg(&W[(size_t)(e + 1) * 768 + 512 + h]), a1);
            a2 = fmaf(xrow[e + 2], __ldg(&W[(size_t)(e + 2) * 768 + 512 + h]), a2);
            a3 = fmaf(xrow[e + 3], __ldg(&W[(size_t)(e + 3) * 768 + 512 + h]), a3);
        }
        float go = (a0 + a1) + (a2 + a3);
        g_oB[b * H_DIM + h] = 1.f / (1.f + expf(-go));
        return;
    }

    __shared__ int toks[TC];
    if (h < TC) toks[h] = __ldg(&X[b * T_LEN + chunk * TC + h]);
    __syncthreads();

    float A = 1.f, Bc = 0.f;
    #pragma unroll 16
    for (int t = 0; t < TC; t++) {
        float2 p = __ldg(&g_Gfz[(size_t)toks[t] * H_DIM + h]);
        float z = p.x, f = p.y;
        A *= f;
        Bc = fmaf(f, Bc - z, z);
    }

    int idx = (b * NCH + chunk) * H_DIM + h;
    g_cA[idx] = A;
    g_cB[idx] = Bc;
}

// ---------------------------------------------------------------------------
// Kernel 3: slim finalize — batched chunk-combine prefetch, precomputed o,
// output projection with block reduction. One CTA per batch row.
// ---------------------------------------------------------------------------
__global__ __launch_bounds__(256) void finalize(
    const float* __restrict__ c0,     // [B, H]
    const float* __restrict__ Wout,   // [H]
    const float* __restrict__ bout,   // [1]
    float*       __restrict__ out)    // [B]
{
    const int b = blockIdx.x;
    const int h = threadIdx.x;

    __shared__ float red[H_DIM];

    // Batched prefetch: 32 independent loads, single latency exposure
    float As[NCH], Bs[NCH];
    #pragma unroll
    for (int j = 0; j < NCH; j++) {
        int idx = (b * NCH + j) * H_DIM + h;
        As[j] = __ldg(&g_cA[idx]);
        Bs[j] = __ldg(&g_cB[idx]);
    }
    float c = __ldg(&c0[b * H_DIM + h]);
    #pragma unroll
    for (int j = 0; j < NCH; j++) c = fmaf(As[j], c, Bs[j]);

    red[h] = __ldg(&g_oB[b * H_DIM + h]) * c * __ldg(&Wout[h]);
    __syncthreads();

    #pragma unroll
    for (int s = 128; s > 0; s >>= 1) {
        if (h < s) red[h] += red[h + s];
        __syncthreads();
    }
    if (h == 0) out[b] = red[0] + bout[0];
}

// ---------------------------------------------------------------------------
extern "C" void kernel_launch(void* const* d_in, const int* in_sizes, int n_in,
                              void* d_out, int out_size)
{
    const int*   X    = (const int*)  d_in[0];   // [B, T] int32
    const float* emb  = (const float*)d_in[1];   // [VOCAB, E]
    const float* Wq   = (const float*)d_in[2];   // [E, 3H]
    const float* bq   = (const float*)d_in[3];   // [3H]
    const float* c0   = (const float*)d_in[4];   // [B, H]
    const float* Wout = (const float*)d_in[5];   // [H, 1]
    const float* bout = (const float*)d_in[6];   // [1]
    float*       out  = (float*)d_out;           // [B, 1]

    (void)in_sizes; (void)n_in; (void)out_size;

    cudaFuncSetAttribute(gemm_gates_mma, cudaFuncAttributeMaxDynamicSharedMemorySize, SMTOT);

    // 0) fp16 conversions (single rounding both operands)
    convert_A<<<VOCAB * 64 / 256, 256>>>(emb);   // 8000 blocks
    convert_B<<<256, 512>>>(Wq);

    // 1) Gate-table GEMM on tensor cores, K=256 fp16
    dim3 ggrid(4, VOCAB / 128);                  // (4, 250)
    gemm_gates_mma<<<ggrid, 256, SMTOT>>>(bq);

    // 2) Parallel chunked scan + overlapped o-gate CTAs
    dim3 sgrid(NCH + 1, BATCH);                  // (17, 64)
    scan_chunks<<<sgrid, 256>>>(X, emb, Wq, bq);

    // 3) Slim combine + output projection
    finalize<<<BATCH, 256>>>(c0, Wout, bout, out);
}

// round 16
// speedup vs baseline: 2.2198x; 1.0245x over previous
#include <cuda_runtime.h>
#include <cuda_fp16.h>
#include <math.h>
#include <stdint.h>

// Problem constants
#define VOCAB 32000
#define E_DIM 256
#define H_DIM 256
#define BATCH 64
#define T_LEN 2048
#define NCH 16                 // time chunks for parallel scan
#define TC (T_LEN / NCH)       // 128 timesteps per chunk

// ---------------- device scratch (allocation-free contract) ----------------
// Interleaved gate table: g_Gfz[v*256 + h] = half2(tanh(z), sigmoid(f)), 32 MB
__device__ __half2 g_Gfz[(size_t)VOCAB * H_DIM];
__device__ float g_cA[BATCH * NCH * H_DIM];          // per-chunk scan coeff A
__device__ float g_cB[BATCH * NCH * H_DIM];          // per-chunk scan coeff B
__device__ float g_oB[BATCH * H_DIM];                // o-gate for last token, per b
// A = emb rounded once to fp16, [VOCAB, 256] (16.4 MB)
__device__ __half g_Ahf[(size_t)VOCAB * 256];
// B rows j=0..511 interleaved (j=2h -> z col h, j=2h+1 -> f col h), K=256 fp16
__device__ __half g_Bhf[(size_t)512 * 256];

static __device__ __forceinline__ uint32_t smem_u32(const void* p) {
    uint32_t a;
    asm("{ .reg .u64 t; cvta.to.shared.u64 t, %1; cvt.u32.u64 %0, t; }" : "=r"(a) : "l"(p));
    return a;
}

// ===========================================================================
// Convert kernels: fp32 -> fp16 (single rounding), GEMM-friendly layouts.
// ===========================================================================
__global__ __launch_bounds__(256) void convert_A(const float* __restrict__ emb)
{
    int idx = blockIdx.x * 256 + threadIdx.x;   // one float4 each; 32000*64 total
    int v = idx >> 6;
    int k = (idx & 63) * 4;
    float4 x = *(const float4*)(emb + (size_t)v * E_DIM + k);
    __half2 h01 = __floats2half2_rn(x.x, x.y);
    __half2 h23 = __floats2half2_rn(x.z, x.w);
    __half* row = g_Ahf + (size_t)v * 256;
    *(__half2*)(row + k)     = h01;
    *(__half2*)(row + k + 2) = h23;
}

__global__ __launch_bounds__(512) void convert_B(const float* __restrict__ W)
{
    int k = blockIdx.x;          // 0..255 (W row)
    int j = threadIdx.x;         // 0..511 interleaved output row
    int src = (j & 1) * 256 + (j >> 1);   // even j -> z col, odd j -> f col
    g_Bhf[(size_t)j * 256 + k] = __float2half(W[(size_t)k * 768 + src]);
}

// ===========================================================================
// Kernel 1: fp16 GEMM on mma.sync m16n8k16, 4-stage cp.async pipeline,
// one __syncthreads per K-iteration. Per CTA: D[128x128] over K=256 (8 iters).
// ===========================================================================
#define STG   20480              // per-stage stride (A tile + B tile)
#define BOFF  10240              // B tile offset within a stage
#define SBIAS 81920              // bias offset
#define SMTOT (SBIAS + 512)
#define NKIT  8

__global__ __launch_bounds__(256, 2) void gemm_gates_mma(const float* __restrict__ bias)
{
    extern __shared__ __align__(128) char dsm[];
    float* sbias = (float*)(dsm + SBIAS);

    const int tid  = threadIdx.x;
    const int lane = tid & 31;
    const int wid  = tid >> 5;
    const int n0   = blockIdx.x * 128;   // interleaved col block (z/f mixed)
    const int m0   = blockIdx.y * 128;   // vocab row base
    const int warp_m = wid & 1;
    const int warp_n = wid >> 1;

    if (tid < 128) {
        int j = n0 + tid;
        sbias[tid] = bias[(j & 1) * 256 + (j >> 1)];
    }

    const uint32_t sbase = smem_u32(dsm);

    // cp.async mapping: per tile 512 16B-chunks; row = tid>>2 (+64), chunk = tid&3
    const int ld_row = tid >> 2;
    const int ld_chk = tid & 3;

    float c[4][4][4];
    #pragma unroll
    for (int i = 0; i < 4; i++)
        #pragma unroll
        for (int j = 0; j < 4; j++)
            #pragma unroll
            for (int q = 0; q < 4; q++) c[i][j][q] = 0.f;

    // ldmatrix lane-dependent base byte-offsets (stage offset added later)
    const uint32_t a_lm = (uint32_t)((warp_m * 64 + (lane & 15)) * 80 + (lane >> 4) * 16);
    const uint32_t b_lm = (uint32_t)((warp_n * 32 + (lane >> 4) * 8 + (lane & 7)) * 80
                                     + ((lane >> 3) & 1) * 16);

#define ISSUE(it) do {                                                             \
    if ((it) < NKIT) {                                                             \
        int buf_ = (it) & 3;                                                       \
        int kk_ = (it) * 32;                                                       \
        _Pragma("unroll")                                                          \
        for (int r_ = 0; r_ < 2; r_++) {                                           \
            int row_ = ld_row + r_ * 64;                                           \
            uint32_t da_ = sbase + buf_ * STG + row_ * 80 + ld_chk * 16;           \
            const __half* ga_ = g_Ahf + (size_t)(m0 + row_) * 256 + kk_ + ld_chk * 8; \
            asm volatile("cp.async.cg.shared.global [%0], [%1], 16;" :: "r"(da_), "l"(ga_)); \
            uint32_t db_ = sbase + buf_ * STG + BOFF + row_ * 80 + ld_chk * 16;    \
            const __half* gb_ = g_Bhf + (size_t)(n0 + row_) * 256 + kk_ + ld_chk * 8; \
            asm volatile("cp.async.cg.shared.global [%0], [%1], 16;" :: "r"(db_), "l"(gb_)); \
        }                                                                          \
    }                                                                              \
    asm volatile("cp.async.commit_group;");                                        \
} while (0)

    ISSUE(0); ISSUE(1); ISSUE(2);

    for (int it = 0; it < NKIT; ++it) {
        const int buf = it & 3;
        asm volatile("cp.async.wait_group 2;");
        __syncthreads();              // stage `it` visible; all warps done with it-1
        ISSUE(it + 3);                // fills buf (it-1)&3 — safe after the sync

        #pragma unroll
        for (int ks = 0; ks < 2; ks++) {
            uint32_t a[4][4], b[4][2];
            #pragma unroll
            for (int mt = 0; mt < 4; mt++) {
                uint32_t addr = sbase + buf * STG + a_lm + mt * (16 * 80) + ks * 32;
                asm volatile("ldmatrix.sync.aligned.m8n8.x4.shared.b16 {%0,%1,%2,%3}, [%4];"
                             : "=r"(a[mt][0]), "=r"(a[mt][1]), "=r"(a[mt][2]), "=r"(a[mt][3])
                             : "r"(addr));
            }
            #pragma unroll
            for (int np = 0; np < 2; np++) {
                uint32_t addr = sbase + buf * STG + BOFF + b_lm + np * (16 * 80) + ks * 32;
                asm volatile("ldmatrix.sync.aligned.m8n8.x4.shared.b16 {%0,%1,%2,%3}, [%4];"
                             : "=r"(b[np * 2][0]), "=r"(b[np * 2][1]),
                               "=r"(b[np * 2 + 1][0]), "=r"(b[np * 2 + 1][1])
                             : "r"(addr));
            }
            #pragma unroll
            for (int mt = 0; mt < 4; mt++)
                #pragma unroll
                for (int nt = 0; nt < 4; nt++)
                    asm volatile(
                        "mma.sync.aligned.m16n8k16.row.col.f32.f16.f16.f32 "
                        "{%0,%1,%2,%3}, {%4,%5,%6,%7}, {%8,%9}, {%0,%1,%2,%3};"
                        : "+f"(c[mt][nt][0]), "+f"(c[mt][nt][1]),
                          "+f"(c[mt][nt][2]), "+f"(c[mt][nt][3])
                        : "r"(a[mt][0]), "r"(a[mt][1]), "r"(a[mt][2]), "r"(a[mt][3]),
                          "r"(b[nt][0]), "r"(b[nt][1]));
        }
    }
#undef ISSUE

    // ---- Epilogue: bias + activation, one half2 (z,f) per h to g_Gfz ----
    #pragma unroll
    for (int mt = 0; mt < 4; mt++) {
        int m = m0 + warp_m * 64 + mt * 16 + (lane >> 2);
        #pragma unroll
        for (int nt = 0; nt < 4; nt++) {
            int nloc = warp_n * 32 + nt * 8 + (lane & 3) * 2;   // even = z, odd = f
            int h = (n0 + nloc) >> 1;
            float vz0 = c[mt][nt][0] + sbias[nloc];
            float vf0 = c[mt][nt][1] + sbias[nloc + 1];
            float vz1 = c[mt][nt][2] + sbias[nloc];
            float vf1 = c[mt][nt][3] + sbias[nloc + 1];
            __half2 o0 = __floats2half2_rn(tanhf(vz0), 1.f / (1.f + expf(-vf0)));
            __half2 o1 = __floats2half2_rn(tanhf(vz1), 1.f / (1.f + expf(-vf1)));
            g_Gfz[(size_t)m * H_DIM + h]       = o0;
            g_Gfz[(size_t)(m + 8) * H_DIM + h] = o1;
        }
    }
}

// ---------------------------------------------------------------------------
// Kernel 2: parallel chunked scan (1024 CTAs) + 64 overlapped o-gate CTAs.
// Table now half2: 4B gather per (t,h) — half the LTS bytes of the fp32 table.
// Recurrence arithmetic stays fp32.
// ---------------------------------------------------------------------------
__global__ __launch_bounds__(256) void scan_chunks(
    const int* __restrict__ X,
    const float* __restrict__ emb,
    const float* __restrict__ W,      // [256, 768]
    const float* __restrict__ bias)   // [768]
{
    const int chunk = blockIdx.x;
    const int b     = blockIdx.y;
    const int h     = threadIdx.x;

    if (chunk == NCH) {
        // ---- o-gate CTA: o_b[h] = sigmoid(emb[tok_last].W[:,512+h] + bias) ----
        __shared__ float xrow[E_DIM];
        const int tok_last = X[b * T_LEN + (T_LEN - 1)];
        xrow[h] = emb[(size_t)tok_last * E_DIM + h];
        __syncthreads();

        float a0 = bias[512 + h], a1 = 0.f, a2 = 0.f, a3 = 0.f;
        #pragma unroll 8
        for (int e = 0; e < E_DIM; e += 4) {
            a0 = fmaf(xrow[e + 0], __ldg(&W[(size_t)(e + 0) * 768 + 512 + h]), a0);
            a1 = fmaf(xrow[e + 1], __ldg(&W[(size_t)(e + 1) * 768 + 512 + h]), a1);
            a2 = fmaf(xrow[e + 2], __ldg(&W[(size_t)(e + 2) * 768 + 512 + h]), a2);
            a3 = fmaf(xrow[e + 3], __ldg(&W[(size_t)(e + 3) * 768 + 512 + h]), a3);
        }
        float go = (a0 + a1) + (a2 + a3);
        g_oB[b * H_DIM + h] = 1.f / (1.f + expf(-go));
        return;
    }

    __shared__ int toks[TC];
    if (h < TC) toks[h] = __ldg(&X[b * T_LEN + chunk * TC + h]);
    __syncthreads();

    float A = 1.f, Bc = 0.f;
    #pragma unroll 16
    for (int t = 0; t < TC; t++) {
        __half2 p = __ldg(&g_Gfz[(size_t)toks[t] * H_DIM + h]);
        float2 pf = __half22float2(p);
        float z = pf.x, f = pf.y;
        A *= f;
        Bc = fmaf(f, Bc - z, z);
    }

    int idx = (b * NCH + chunk) * H_DIM + h;
    g_cA[idx] = A;
    g_cB[idx] = Bc;
}

// ---------------------------------------------------------------------------
// Kernel 3: slim finalize — batched chunk-combine prefetch, precomputed o,
// output projection with block reduction. One CTA per batch row.
// ---------------------------------------------------------------------------
__global__ __launch_bounds__(256) void finalize(
    const float* __restrict__ c0,     // [B, H]
    const float* __restrict__ Wout,   // [H]
    const float* __restrict__ bout,   // [1]
    float*       __restrict__ out)    // [B]
{
    const int b = blockIdx.x;
    const int h = threadIdx.x;

    __shared__ float red[H_DIM];

    // Batched prefetch: 32 independent loads, single latency exposure
    float As[NCH], Bs[NCH];
    #pragma unroll
    for (int j = 0; j < NCH; j++) {
        int idx = (b * NCH + j) * H_DIM + h;
        As[j] = __ldg(&g_cA[idx]);
        Bs[j] = __ldg(&g_cB[idx]);
    }
    float c = __ldg(&c0[b * H_DIM + h]);
    #pragma unroll
    for (int j = 0; j < NCH; j++) c = fmaf(As[j], c, Bs[j]);

    red[h] = __ldg(&g_oB[b * H_DIM + h]) * c * __ldg(&Wout[h]);
    __syncthreads();

    #pragma unroll
    for (int s = 128; s > 0; s >>= 1) {
        if (h < s) red[h] += red[h + s];
        __syncthreads();
    }
    if (h == 0) out[b] = red[0] + bout[0];
}

// ---------------------------------------------------------------------------
extern "C" void kernel_launch(void* const* d_in, const int* in_sizes, int n_in,
                              void* d_out, int out_size)
{
    const int*   X    = (const int*)  d_in[0];   // [B, T] int32
    const float* emb  = (const float*)d_in[1];   // [VOCAB, E]
    const float* Wq   = (const float*)d_in[2];   // [E, 3H]
    const float* bq   = (const float*)d_in[3];   // [3H]
    const float* c0   = (const float*)d_in[4];   // [B, H]
    const float* Wout = (const float*)d_in[5];   // [H, 1]
    const float* bout = (const float*)d_in[6];   // [1]
    float*       out  = (float*)d_out;           // [B, 1]

    (void)in_sizes; (void)n_in; (void)out_size;

    cudaFuncSetAttribute(gemm_gates_mma, cudaFuncAttributeMaxDynamicSharedMemorySize, SMTOT);

    // 0) fp16 conversions (single rounding both operands)
    convert_A<<<VOCAB * 64 / 256, 256>>>(emb);   // 8000 blocks
    convert_B<<<256, 512>>>(Wq);

    // 1) Gate-table GEMM on tensor cores, K=256 fp16
    dim3 ggrid(4, VOCAB / 128);                  // (4, 250)
    gemm_gates_mma<<<ggrid, 256, SMTOT>>>(bq);

    // 2) Parallel chunked scan + overlapped o-gate CTAs (half2 table)
    dim3 sgrid(NCH + 1, BATCH);                  // (17, 64)
    scan_chunks<<<sgrid, 256>>>(X, emb, Wq, bq);

    // 3) Slim combine + output projection
    finalize<<<BATCH, 256>>>(c0, Wout, bout, out);
}

// round 17
// speedup vs baseline: 2.3694x; 1.0674x over previous
#include <cuda_runtime.h>
#include <cuda_fp16.h>
#include <math.h>
#include <stdint.h>

// Problem constants
#define VOCAB 32000
#define E_DIM 256
#define H_DIM 256
#define BATCH 64
#define T_LEN 2048
#define NCH 16                 // CTA chunks (x-dim of scan grid)
#define TC (T_LEN / NCH)       // 128 timesteps per CTA chunk
#define NCH2 32                // affine sub-chunks (2 per CTA chunk, 64 t each)

// ---------------- device scratch (allocation-free contract) ----------------
// Interleaved gate table: g_Gfz[v*256 + h] = half2(tanh(z), sigmoid(f)), 32 MB
__device__ __half2 g_Gfz[(size_t)VOCAB * H_DIM];
__device__ float g_cA[BATCH * NCH2 * H_DIM];         // per-sub-chunk coeff A
__device__ float g_cB[BATCH * NCH2 * H_DIM];         // per-sub-chunk coeff B
__device__ float g_oB[BATCH * H_DIM];                // o-gate for last token, per b
// A = emb rounded once to fp16, [VOCAB, 256] (16.4 MB)
__device__ __half g_Ahf[(size_t)VOCAB * 256];
// B rows j=0..511 interleaved (j=2h -> z col h, j=2h+1 -> f col h), K=256 fp16
__device__ __half g_Bhf[(size_t)512 * 256];

static __device__ __forceinline__ uint32_t smem_u32(const void* p) {
    uint32_t a;
    asm("{ .reg .u64 t; cvta.to.shared.u64 t, %1; cvt.u32.u64 %0, t; }" : "=r"(a) : "l"(p));
    return a;
}

// ===========================================================================
// convert_AB: fused A (blocks 0..7999) + B (blocks 8000..8255) conversion.
// ===========================================================================
__global__ __launch_bounds__(256) void convert_AB(
    const float* __restrict__ emb, const float* __restrict__ W)
{
    if (blockIdx.x < 8000) {
        int idx = blockIdx.x * 256 + threadIdx.x;   // one float4 each
        int v = idx >> 6;
        int k = (idx & 63) * 4;
        float4 x = *(const float4*)(emb + (size_t)v * E_DIM + k);
        __half2 h01 = __floats2half2_rn(x.x, x.y);
        __half2 h23 = __floats2half2_rn(x.z, x.w);
        __half* row = g_Ahf + (size_t)v * 256;
        *(__half2*)(row + k)     = h01;
        *(__half2*)(row + k + 2) = h23;
    } else {
        int k = blockIdx.x - 8000;   // 0..255 (W row)
        #pragma unroll
        for (int j = threadIdx.x; j < 512; j += 256) {
            int src = (j & 1) * 256 + (j >> 1);   // even j -> z col, odd -> f col
            g_Bhf[(size_t)j * 256 + k] = __float2half(W[(size_t)k * 768 + src]);
        }
    }
}

// ===========================================================================
// Kernel 1: fp16 GEMM on mma.sync m16n8k16, 4-stage cp.async pipeline,
// one __syncthreads per K-iteration. Per CTA: D[128x128] over K=256 (8 iters).
// (byte-identical mainloop to the 70.5us winner)
// ===========================================================================
#define STG   20480              // per-stage stride (A tile + B tile)
#define BOFF  10240              // B tile offset within a stage
#define SBIAS 81920              // bias offset
#define SMTOT (SBIAS + 512)
#define NKIT  8

__global__ __launch_bounds__(256, 2) void gemm_gates_mma(const float* __restrict__ bias)
{
    extern __shared__ __align__(128) char dsm[];
    float* sbias = (float*)(dsm + SBIAS);

    const int tid  = threadIdx.x;
    const int lane = tid & 31;
    const int wid  = tid >> 5;
    const int n0   = blockIdx.x * 128;   // interleaved col block (z/f mixed)
    const int m0   = blockIdx.y * 128;   // vocab row base
    const int warp_m = wid & 1;
    const int warp_n = wid >> 1;

    if (tid < 128) {
        int j = n0 + tid;
        sbias[tid] = bias[(j & 1) * 256 + (j >> 1)];
    }

    const uint32_t sbase = smem_u32(dsm);

    const int ld_row = tid >> 2;
    const int ld_chk = tid & 3;

    float c[4][4][4];
    #pragma unroll
    for (int i = 0; i < 4; i++)
        #pragma unroll
        for (int j = 0; j < 4; j++)
            #pragma unroll
            for (int q = 0; q < 4; q++) c[i][j][q] = 0.f;

    const uint32_t a_lm = (uint32_t)((warp_m * 64 + (lane & 15)) * 80 + (lane >> 4) * 16);
    const uint32_t b_lm = (uint32_t)((warp_n * 32 + (lane >> 4) * 8 + (lane & 7)) * 80
                                     + ((lane >> 3) & 1) * 16);

#define ISSUE(it) do {                                                             \
    if ((it) < NKIT) {                                                             \
        int buf_ = (it) & 3;                                                       \
        int kk_ = (it) * 32;                                                       \
        _Pragma("unroll")                                                          \
        for (int r_ = 0; r_ < 2; r_++) {                                           \
            int row_ = ld_row + r_ * 64;                                           \
            uint32_t da_ = sbase + buf_ * STG + row_ * 80 + ld_chk * 16;           \
            const __half* ga_ = g_Ahf + (size_t)(m0 + row_) * 256 + kk_ + ld_chk * 8; \
            asm volatile("cp.async.cg.shared.global [%0], [%1], 16;" :: "r"(da_), "l"(ga_)); \
            uint32_t db_ = sbase + buf_ * STG + BOFF + row_ * 80 + ld_chk * 16;    \
            const __half* gb_ = g_Bhf + (size_t)(n0 + row_) * 256 + kk_ + ld_chk * 8; \
            asm volatile("cp.async.cg.shared.global [%0], [%1], 16;" :: "r"(db_), "l"(gb_)); \
        }                                                                          \
    }                                                                              \
    asm volatile("cp.async.commit_group;");                                        \
} while (0)

    ISSUE(0); ISSUE(1); ISSUE(2);

    for (int it = 0; it < NKIT; ++it) {
        const int buf = it & 3;
        asm volatile("cp.async.wait_group 2;");
        __syncthreads();
        ISSUE(it + 3);

        #pragma unroll
        for (int ks = 0; ks < 2; ks++) {
            uint32_t a[4][4], b[4][2];
            #pragma unroll
            for (int mt = 0; mt < 4; mt++) {
                uint32_t addr = sbase + buf * STG + a_lm + mt * (16 * 80) + ks * 32;
                asm volatile("ldmatrix.sync.aligned.m8n8.x4.shared.b16 {%0,%1,%2,%3}, [%4];"
                             : "=r"(a[mt][0]), "=r"(a[mt][1]), "=r"(a[mt][2]), "=r"(a[mt][3])
                             : "r"(addr));
            }
            #pragma unroll
            for (int np = 0; np < 2; np++) {
                uint32_t addr = sbase + buf * STG + BOFF + b_lm + np * (16 * 80) + ks * 32;
                asm volatile("ldmatrix.sync.aligned.m8n8.x4.shared.b16 {%0,%1,%2,%3}, [%4];"
                             : "=r"(b[np * 2][0]), "=r"(b[np * 2][1]),
                               "=r"(b[np * 2 + 1][0]), "=r"(b[np * 2 + 1][1])
                             : "r"(addr));
            }
            #pragma unroll
            for (int mt = 0; mt < 4; mt++)
                #pragma unroll
                for (int nt = 0; nt < 4; nt++)
                    asm volatile(
                        "mma.sync.aligned.m16n8k16.row.col.f32.f16.f16.f32 "
                        "{%0,%1,%2,%3}, {%4,%5,%6,%7}, {%8,%9}, {%0,%1,%2,%3};"
                        : "+f"(c[mt][nt][0]), "+f"(c[mt][nt][1]),
                          "+f"(c[mt][nt][2]), "+f"(c[mt][nt][3])
                        : "r"(a[mt][0]), "r"(a[mt][1]), "r"(a[mt][2]), "r"(a[mt][3]),
                          "r"(b[nt][0]), "r"(b[nt][1]));
        }
    }
#undef ISSUE

    // ---- Epilogue: bias + activation, one half2 (z,f) per h to g_Gfz ----
    #pragma unroll
    for (int mt = 0; mt < 4; mt++) {
        int m = m0 + warp_m * 64 + mt * 16 + (lane >> 2);
        #pragma unroll
        for (int nt = 0; nt < 4; nt++) {
            int nloc = warp_n * 32 + nt * 8 + (lane & 3) * 2;   // even = z, odd = f
            int h = (n0 + nloc) >> 1;
            float vz0 = c[mt][nt][0] + sbias[nloc];
            float vf0 = c[mt][nt][1] + sbias[nloc + 1];
            float vz1 = c[mt][nt][2] + sbias[nloc];
            float vf1 = c[mt][nt][3] + sbias[nloc + 1];
            __half2 o0 = __floats2half2_rn(tanhf(vz0), 1.f / (1.f + expf(-vf0)));
            __half2 o1 = __floats2half2_rn(tanhf(vz1), 1.f / (1.f + expf(-vf1)));
            g_Gfz[(size_t)m * H_DIM + h]       = o0;
            g_Gfz[(size_t)(m + 8) * H_DIM + h] = o1;
        }
    }
}

// ---------------------------------------------------------------------------
// Kernel 2: parallel chunked scan, channel-paired. Thread i handles h=2i,2i+1
// with one LDG.64 per timestep; half-CTAs cover 64-t sub-chunks (NCH2=32).
// + 64 overlapped o-gate CTAs (blockIdx.x == NCH).
// ---------------------------------------------------------------------------
__global__ __launch_bounds__(256) void scan_chunks(
    const int* __restrict__ X,
    const float* __restrict__ emb,
    const float* __restrict__ W,      // [256, 768]
    const float* __restrict__ bias)   // [768]
{
    const int chunk = blockIdx.x;
    const int b     = blockIdx.y;
    const int tid   = threadIdx.x;

    if (chunk == NCH) {
        // ---- o-gate CTA: o_b[h] = sigmoid(emb[tok_last].W[:,512+h] + bias) ----
        const int h = tid;
        __shared__ float xrow[E_DIM];
        const int tok_last = X[b * T_LEN + (T_LEN - 1)];
        xrow[h] = emb[(size_t)tok_last * E_DIM + h];
        __syncthreads();

        float a0 = bias[512 + h], a1 = 0.f, a2 = 0.f, a3 = 0.f;
        #pragma unroll 8
        for (int e = 0; e < E_DIM; e += 4) {
            a0 = fmaf(xrow[e + 0], __ldg(&W[(size_t)(e + 0) * 768 + 512 + h]), a0);
            a1 = fmaf(xrow[e + 1], __ldg(&W[(size_t)(e + 1) * 768 + 512 + h]), a1);
            a2 = fmaf(xrow[e + 2], __ldg(&W[(size_t)(e + 2) * 768 + 512 + h]), a2);
            a3 = fmaf(xrow[e + 3], __ldg(&W[(size_t)(e + 3) * 768 + 512 + h]), a3);
        }
        float go = (a0 + a1) + (a2 + a3);
        g_oB[b * H_DIM + h] = 1.f / (1.f + expf(-go));
        return;
    }

    const int sub = tid >> 7;       // 0: t in [0,64), 1: t in [64,128)
    const int i   = tid & 127;      // h-pair index; h = 2i, 2i+1

    __shared__ int toks[TC];
    if (tid < TC) toks[tid] = __ldg(&X[b * T_LEN + chunk * TC + tid]);
    __syncthreads();

    const __half2* rowbase = g_Gfz + 2 * i;
    float A0 = 1.f, B0 = 0.f, A1 = 1.f, B1 = 0.f;
    const int tbase = sub * 64;

    #pragma unroll 8
    for (int t = 0; t < 64; t++) {
        int tok = toks[tbase + t];
        uint2 raw = __ldg((const uint2*)(rowbase + (size_t)tok * H_DIM));
        float2 q0 = __half22float2(*(__half2*)&raw.x);   // (z,f) for h=2i
        float2 q1 = __half22float2(*(__half2*)&raw.y);   // (z,f) for h=2i+1
        A0 *= q0.y;  B0 = fmaf(q0.y, B0 - q0.x, q0.x);
        A1 *= q1.y;  B1 = fmaf(q1.y, B1 - q1.x, q1.x);
    }

    int cidx = (b * NCH2 + chunk * 2 + sub) * H_DIM + 2 * i;
    *(float2*)&g_cA[cidx] = make_float2(A0, A1);
    *(float2*)&g_cB[cidx] = make_float2(B0, B1);
}

// ---------------------------------------------------------------------------
// Kernel 3: slim finalize — 32 sub-chunk combine (batched prefetch),
// precomputed o, output projection with block reduction.
// ---------------------------------------------------------------------------
__global__ __launch_bounds__(256) void finalize(
    const float* __restrict__ c0,     // [B, H]
    const float* __restrict__ Wout,   // [H]
    const float* __restrict__ bout,   // [1]
    float*       __restrict__ out)    // [B]
{
    const int b = blockIdx.x;
    const int h = threadIdx.x;

    __shared__ float red[H_DIM];

    float As[NCH2], Bs[NCH2];
    #pragma unroll
    for (int j = 0; j < NCH2; j++) {
        int idx = (b * NCH2 + j) * H_DIM + h;
        As[j] = __ldg(&g_cA[idx]);
        Bs[j] = __ldg(&g_cB[idx]);
    }
    float c = __ldg(&c0[b * H_DIM + h]);
    #pragma unroll
    for (int j = 0; j < NCH2; j++) c = fmaf(As[j], c, Bs[j]);

    red[h] = __ldg(&g_oB[b * H_DIM + h]) * c * __ldg(&Wout[h]);
    __syncthreads();

    #pragma unroll
    for (int s = 128; s > 0; s >>= 1) {
        if (h < s) red[h] += red[h + s];
        __syncthreads();
    }
    if (h == 0) out[b] = red[0] + bout[0];
}

// ---------------------------------------------------------------------------
extern "C" void kernel_launch(void* const* d_in, const int* in_sizes, int n_in,
                              void* d_out, int out_size)
{
    const int*   X    = (const int*)  d_in[0];   // [B, T] int32
    const float* emb  = (const float*)d_in[1];   // [VOCAB, E]
    const float* Wq   = (const float*)d_in[2];   // [E, 3H]
    const float* bq   = (const float*)d_in[3];   // [3H]
    const float* c0   = (const float*)d_in[4];   // [B, H]
    const float* Wout = (const float*)d_in[5];   // [H, 1]
    const float* bout = (const float*)d_in[6];   // [1]
    float*       out  = (float*)d_out;           // [B, 1]

    (void)in_sizes; (void)n_in; (void)out_size;

    cudaFuncSetAttribute(gemm_gates_mma, cudaFuncAttributeMaxDynamicSharedMemorySize, SMTOT);

    // 0) fused fp16 conversions (A: 8000 blocks, B: 256 blocks)
    convert_AB<<<8256, 256>>>(emb, Wq);

    // 1) Gate-table GEMM on tensor cores, K=256 fp16
    dim3 ggrid(4, VOCAB / 128);                  // (4, 250)
    gemm_gates_mma<<<ggrid, 256, SMTOT>>>(bq);

    // 2) Channel-paired chunked scan + overlapped o-gate CTAs
    dim3 sgrid(NCH + 1, BATCH);                  // (17, 64)
    scan_chunks<<<sgrid, 256>>>(X, emb, Wq, bq);

    // 3) Slim combine + output projection
    finalize<<<BATCH, 256>>>(c0, Wout, bout, out);
}